// round 11
// baseline (speedup 1.0000x reference)
#include <cuda_runtime.h>
#include <stdint.h>

#define BB   16
#define CH   3
#define HH   1024
#define WW   1024
#define NCRACK 8
#define PIX    (HH * WW)
#define CRACK_VAL 0.05f
#define ROWS_PER_BLK 4

// ---------------------------------------------------------------------------
// One block per (4-row group, batch): 4 consecutive rows x 3 channels.
// 12 LDG.128 issued up front (192B in flight per thread); warps 0..3 build
// the four row masks concurrently via shuffles; one barrier; apply + store.
//
// Closed-form Bresenham inversion (validated rel_err=0 in R2-R9):
//   x-major (dx>=dy), m = sy*(y-y0) in [0,dy]:
//     m==0: t in [0, floor(dx/(2dy))] (dy==0: [0,dx])
//     m>=1: t in [floor(dx(2m-1)/(2dy))+1, floor(dx(2m+1)/(2dy))], t<=dx
//     x = x0 + sx*t (contiguous interval)
//   y-major: single pixel x = x0 + sx*max(0, ceil((2t*dx-dy)/(2dy)))
// ---------------------------------------------------------------------------
__global__ __launch_bounds__(256) void fused_crack_kernel(
    const float4* __restrict__ x, float4* __restrict__ out,
    const int* __restrict__ ep)
{
    __shared__ unsigned rowmask[ROWS_PER_BLK][32];

    const unsigned row0 = blockIdx.x * ROWS_PER_BLK;
    const unsigned b    = blockIdx.y;

    // ---- issue all 12 streaming loads first ----
    const unsigned p4   = row0 * 256u + threadIdx.x;
    const unsigned base = b * CH * (PIX / 4) + p4;

    float4 v[ROWS_PER_BLK][CH];
    #pragma unroll
    for (int r = 0; r < ROWS_PER_BLK; r++)
        #pragma unroll
        for (int c = 0; c < CH; c++)
            v[r][c] = x[base + (unsigned)r * 256u + (unsigned)c * (PIX / 4)];

    // ---- warps 0..3 build the four row masks (shuffle-based) ----
    if (threadIdx.x < 32u * ROWS_PER_BLK) {
        const unsigned wrp  = threadIdx.x >> 5;            // 0..3 -> row0+wrp
        const unsigned lane = threadIdx.x & 31u;
        const int      y    = (int)(row0 + wrp);

        int xlo = 1, xhi = 0;                              // empty interval
        if (lane < NCRACK) {
            const int4 e = *(const int4*)(ep + (b * NCRACK + lane) * 4); // (y0,x0,y1,x1)
            int y0 = e.x, x0 = e.y, y1 = e.z, x1 = e.w;
            int dx = abs(x1 - x0);
            int dy = abs(y1 - y0);
            int sx = (x0 < x1) ? 1 : -1;
            int sy = (y0 < y1) ? 1 : -1;

            if (dx >= dy) {
                int m = sy * (y - y0);
                if (m >= 0 && m <= dy) {
                    int tlo, thi;
                    if (dy == 0)      { tlo = 0; thi = dx; }
                    else if (m == 0)  { tlo = 0; thi = dx / (2 * dy); }
                    else {
                        tlo = (dx * (2 * m - 1)) / (2 * dy) + 1;
                        thi = (dx * (2 * m + 1)) / (2 * dy);
                    }
                    thi = min(thi, dx);
                    int xa = x0 + sx * tlo;
                    int xb = x0 + sx * thi;
                    xlo = min(xa, xb);
                    xhi = max(xa, xb);
                }
            } else {
                int t = sy * (y - y0);
                if (t >= 0 && t <= dy) {
                    int a  = 2 * t * dx - dy;
                    int b2 = 2 * dy;
                    int k  = max(0, (a + b2 - 1) / b2);
                    xlo = xhi = x0 + sx * k;
                }
            }
        }

        const int wbase = (int)(lane * 32u);
        unsigned w = 0;
        #pragma unroll
        for (int i = 0; i < NCRACK; i++) {
            int lo = __shfl_sync(0xFFFFFFFFu, xlo, i);
            int hi = __shfl_sync(0xFFFFFFFFu, xhi, i);
            lo = max(lo - wbase, 0);
            hi = min(hi - wbase, 31);
            if (lo <= hi) {
                int len = hi - lo + 1;
                w |= (0xFFFFFFFFu >> (32 - len)) << lo;
            }
        }
        rowmask[wrp][lane] = w;
    }
    __syncthreads();

    const unsigned sh = (threadIdx.x & 7u) * 4u;
    const unsigned wi = threadIdx.x >> 3;

    #define APPLY(vv, m) do { \
        (vv).x = ((m) & 1u) ? CRACK_VAL : fminf(fmaxf((vv).x, 0.0f), 1.0f); \
        (vv).y = ((m) & 2u) ? CRACK_VAL : fminf(fmaxf((vv).y, 0.0f), 1.0f); \
        (vv).z = ((m) & 4u) ? CRACK_VAL : fminf(fmaxf((vv).z, 0.0f), 1.0f); \
        (vv).w = ((m) & 8u) ? CRACK_VAL : fminf(fmaxf((vv).w, 0.0f), 1.0f); \
    } while (0)

    #pragma unroll
    for (int r = 0; r < ROWS_PER_BLK; r++) {
        const unsigned m = (rowmask[r][wi] >> sh) & 0xFu;
        #pragma unroll
        for (int c = 0; c < CH; c++)
            APPLY(v[r][c], m);
    }

    #pragma unroll
    for (int r = 0; r < ROWS_PER_BLK; r++)
        #pragma unroll
        for (int c = 0; c < CH; c++)
            out[base + (unsigned)r * 256u + (unsigned)c * (PIX / 4)] = v[r][c];
}

// ---------------------------------------------------------------------------
extern "C" void kernel_launch(void* const* d_in, const int* in_sizes, int n_in,
                              void* d_out, int out_size) {
    const float* x   = (const float*)d_in[0];   // [16,3,1024,1024] f32
    const int*   ep  = (const int*)d_in[1];     // [16,8,4] i32
    float*       out = (float*)d_out;

    dim3 grid(HH / ROWS_PER_BLK, BB);            // one block per (4 rows, batch)
    fused_crack_kernel<<<grid, 256>>>((const float4*)x, (float4*)out, ep);
}

// round 12
// speedup vs baseline: 1.0086x; 1.0086x over previous
#include <cuda_runtime.h>
#include <stdint.h>

#define BB   16
#define CH   3
#define HH   1024
#define WW   1024
#define NCRACK 8
#define PIX    (HH * WW)
#define CRACK_VAL 0.05f

// ---------------------------------------------------------------------------
// One block per (row-pair, batch): 2 consecutive rows x 3 channels.
// 6 LDG.128 issued up front; warps 0,1 build the two row masks via shuffles;
// one barrier; apply; stores use __stcs (evict-first: out is never re-read,
// keep the write stream from churning L2 so read-side residency survives).
//
// Closed-form Bresenham inversion (validated rel_err=0 in R2-R11):
//   x-major (dx>=dy), m = sy*(y-y0) in [0,dy]:
//     m==0: t in [0, floor(dx/(2dy))] (dy==0: [0,dx])
//     m>=1: t in [floor(dx(2m-1)/(2dy))+1, floor(dx(2m+1)/(2dy))], t<=dx
//     x = x0 + sx*t (contiguous interval)
//   y-major: single pixel x = x0 + sx*max(0, ceil((2t*dx-dy)/(2dy)))
// ---------------------------------------------------------------------------
__global__ __launch_bounds__(256) void fused_crack_kernel(
    const float4* __restrict__ x, float4* __restrict__ out,
    const int* __restrict__ ep)
{
    __shared__ unsigned rowmask[2][32];      // 1024-bit mask per row

    const unsigned row0 = blockIdx.x * 2u;
    const unsigned b    = blockIdx.y;

    // ---- issue all 6 streaming loads first ----
    const unsigned p4   = row0 * 256u + threadIdx.x;
    const unsigned base = b * CH * (PIX / 4) + p4;         // row1 = base + 256

    float4 v0 = x[base];
    float4 v1 = x[base +     (PIX / 4)];
    float4 v2 = x[base + 2 * (PIX / 4)];
    float4 v3 = x[base + 256u];
    float4 v4 = x[base + 256u +     (PIX / 4)];
    float4 v5 = x[base + 256u + 2 * (PIX / 4)];

    // ---- warps 0,1 build the two row masks (shuffle-based) ----
    if (threadIdx.x < 64) {
        const unsigned wrp  = threadIdx.x >> 5;            // 0 or 1 -> row0+wrp
        const unsigned lane = threadIdx.x & 31u;
        const int      y    = (int)(row0 + wrp);

        int xlo = 1, xhi = 0;                              // empty interval
        if (lane < NCRACK) {
            const int4 e = *(const int4*)(ep + (b * NCRACK + lane) * 4); // (y0,x0,y1,x1)
            int y0 = e.x, x0 = e.y, y1 = e.z, x1 = e.w;
            int dx = abs(x1 - x0);
            int dy = abs(y1 - y0);
            int sx = (x0 < x1) ? 1 : -1;
            int sy = (y0 < y1) ? 1 : -1;

            if (dx >= dy) {
                int m = sy * (y - y0);
                if (m >= 0 && m <= dy) {
                    int tlo, thi;
                    if (dy == 0)      { tlo = 0; thi = dx; }
                    else if (m == 0)  { tlo = 0; thi = dx / (2 * dy); }
                    else {
                        tlo = (dx * (2 * m - 1)) / (2 * dy) + 1;
                        thi = (dx * (2 * m + 1)) / (2 * dy);
                    }
                    thi = min(thi, dx);
                    int xa = x0 + sx * tlo;
                    int xb = x0 + sx * thi;
                    xlo = min(xa, xb);
                    xhi = max(xa, xb);
                }
            } else {
                int t = sy * (y - y0);
                if (t >= 0 && t <= dy) {
                    int a  = 2 * t * dx - dy;
                    int b2 = 2 * dy;
                    int k  = max(0, (a + b2 - 1) / b2);
                    xlo = xhi = x0 + sx * k;
                }
            }
        }

        const int wbase = (int)(lane * 32u);
        unsigned w = 0;
        #pragma unroll
        for (int i = 0; i < NCRACK; i++) {
            int lo = __shfl_sync(0xFFFFFFFFu, xlo, i);
            int hi = __shfl_sync(0xFFFFFFFFu, xhi, i);
            lo = max(lo - wbase, 0);
            hi = min(hi - wbase, 31);
            if (lo <= hi) {
                int len = hi - lo + 1;
                w |= (0xFFFFFFFFu >> (32 - len)) << lo;
            }
        }
        rowmask[wrp][lane] = w;
    }
    __syncthreads();

    const unsigned sh = (threadIdx.x & 7u) * 4u;
    const unsigned wi = threadIdx.x >> 3;
    const unsigned m0 = (rowmask[0][wi] >> sh) & 0xFu;
    const unsigned m1 = (rowmask[1][wi] >> sh) & 0xFu;

    #define APPLY(v, m) do { \
        (v).x = ((m) & 1u) ? CRACK_VAL : fminf(fmaxf((v).x, 0.0f), 1.0f); \
        (v).y = ((m) & 2u) ? CRACK_VAL : fminf(fmaxf((v).y, 0.0f), 1.0f); \
        (v).z = ((m) & 4u) ? CRACK_VAL : fminf(fmaxf((v).z, 0.0f), 1.0f); \
        (v).w = ((m) & 8u) ? CRACK_VAL : fminf(fmaxf((v).w, 0.0f), 1.0f); \
    } while (0)

    APPLY(v0, m0); APPLY(v1, m0); APPLY(v2, m0);
    APPLY(v3, m1); APPLY(v4, m1); APPLY(v5, m1);

    __stcs(&out[base],                        v0);
    __stcs(&out[base +     (PIX / 4)],        v1);
    __stcs(&out[base + 2 * (PIX / 4)],        v2);
    __stcs(&out[base + 256u],                 v3);
    __stcs(&out[base + 256u +     (PIX / 4)], v4);
    __stcs(&out[base + 256u + 2 * (PIX / 4)], v5);
}

// ---------------------------------------------------------------------------
extern "C" void kernel_launch(void* const* d_in, const int* in_sizes, int n_in,
                              void* d_out, int out_size) {
    const float* x   = (const float*)d_in[0];   // [16,3,1024,1024] f32
    const int*   ep  = (const int*)d_in[1];     // [16,8,4] i32
    float*       out = (float*)d_out;

    dim3 grid(HH / 2, BB);                       // one block per (row-pair, batch)
    fused_crack_kernel<<<grid, 256>>>((const float4*)x, (float4*)out, ep);
}